// round 2
// baseline (speedup 1.0000x reference)
#include <cuda_runtime.h>
#include <cuda_bf16.h>
#include <math.h>

// PositionCollapseLoss: per batch covariance of pos (channels 0:3 of 14),
// eigvals of 3x3 symmetric, loss = -mean(log(clip(lmax/lmin,1,1e6)))
//
// Kernel 1: 9 raw moments per (batch, chunk) -> deterministic partials.
// Kernel 2: fp64 finalize (cov, analytic 3x3 eigvals, loss).

#define B_DIM   32
#define N_PTS   65536
#define N_CH    14
#define CHUNKS  32          // blocks per batch
#define THREADS 256
#define PTS_PER_BLK (N_PTS / CHUNKS)   // 2048

__device__ float g_part[B_DIM * CHUNKS][9];

__global__ __launch_bounds__(THREADS)
void moments_kernel(const float* __restrict__ g) {
    const int blk = blockIdx.x;                 // 0 .. B*CHUNKS-1
    const int b   = blk / CHUNKS;
    const int c   = blk % CHUNKS;
    const int n0  = c * PTS_PER_BLK;

    const float* __restrict__ base = g + (size_t)b * N_PTS * N_CH;

    float sx = 0.f, sy = 0.f, sz = 0.f;
    float sxx = 0.f, sxy = 0.f, sxz = 0.f;
    float syy = 0.f, syz = 0.f, szz = 0.f;

    #pragma unroll 4
    for (int i = threadIdx.x; i < PTS_PER_BLK; i += THREADS) {
        const size_t off = (size_t)(n0 + i) * N_CH;
        // 56-byte point stride => always 8-byte aligned: float2 + scalar
        const float2 xy = *reinterpret_cast<const float2*>(base + off);
        const float  z  = base[off + 2];
        const float x = xy.x, y = xy.y;
        sx += x;  sy += y;  sz += z;
        sxx += x * x;  sxy += x * y;  sxz += x * z;
        syy += y * y;  syz += y * z;  szz += z * z;
    }

    float s[9] = {sx, sy, sz, sxx, sxy, sxz, syy, syz, szz};

    // warp tree-reduce all 9
    #pragma unroll
    for (int k = 0; k < 9; ++k) {
        #pragma unroll
        for (int m = 16; m > 0; m >>= 1)
            s[k] += __shfl_xor_sync(0xffffffffu, s[k], m);
    }

    __shared__ float sm[THREADS / 32][9];
    const int warp = threadIdx.x >> 5;
    const int lane = threadIdx.x & 31;
    if (lane == 0) {
        #pragma unroll
        for (int k = 0; k < 9; ++k) sm[warp][k] = s[k];
    }
    __syncthreads();

    if (warp == 0) {
        #pragma unroll
        for (int k = 0; k < 9; ++k) {
            float v = (lane < (THREADS / 32)) ? sm[lane][k] : 0.f;
            #pragma unroll
            for (int m = 4; m > 0; m >>= 1)
                v += __shfl_xor_sync(0xffffffffu, v, m);
            if (lane == 0) g_part[blk][k] = v;
        }
    }
}

__device__ __forceinline__ double sanitize_d(double x) {
    if (isnan(x)) x = 0.0;
    if (x >  1.0e6) x =  1.0e6;
    if (x < -1.0e6) x = -1.0e6;
    return x;
}

__global__ void finalize_kernel(float* __restrict__ out) {
    const int b = threadIdx.x;   // 0..31, one batch per thread
    double S[9];
    #pragma unroll
    for (int k = 0; k < 9; ++k) S[k] = 0.0;
    for (int c = 0; c < CHUNKS; ++c) {
        #pragma unroll
        for (int k = 0; k < 9; ++k)
            S[k] += (double)g_part[b * CHUNKS + c][k];
    }

    const double invN = 1.0 / (double)N_PTS;
    const double mx = S[0] * invN, my = S[1] * invN, mz = S[2] * invN;
    double cxx = S[3] * invN - mx * mx;
    double cxy = S[4] * invN - mx * my;
    double cxz = S[5] * invN - mx * mz;
    double cyy = S[6] * invN - my * my;
    double cyz = S[7] * invN - my * mz;
    double czz = S[8] * invN - mz * mz;

    cxx = sanitize_d(cxx); cxy = sanitize_d(cxy); cxz = sanitize_d(cxz);
    cyy = sanitize_d(cyy); cyz = sanitize_d(cyz); czz = sanitize_d(czz);

    // Analytic eigenvalues of symmetric 3x3 (trigonometric method)
    const double q  = (cxx + cyy + czz) / 3.0;
    const double p1 = cxy * cxy + cxz * cxz + cyz * cyz;
    const double p2 = (cxx - q) * (cxx - q) + (cyy - q) * (cyy - q)
                    + (czz - q) * (czz - q) + 2.0 * p1;

    double emax, emin;
    if (p2 <= 0.0) {
        emax = q; emin = q;
    } else {
        const double p = sqrt(p2 / 6.0);
        const double ip = 1.0 / p;
        const double b11 = (cxx - q) * ip, b22 = (cyy - q) * ip, b33 = (czz - q) * ip;
        const double b12 = cxy * ip, b13 = cxz * ip, b23 = cyz * ip;
        double detB = b11 * (b22 * b33 - b23 * b23)
                    - b12 * (b12 * b33 - b23 * b13)
                    + b13 * (b12 * b23 - b22 * b13);
        double r = detB * 0.5;
        if (r < -1.0) r = -1.0;
        if (r >  1.0) r =  1.0;
        const double phi = acos(r) / 3.0;
        emax = q + 2.0 * p * cos(phi);
        emin = q + 2.0 * p * cos(phi + 2.0 * 3.14159265358979323846 / 3.0);
    }

    emax = sanitize_d(emax);
    emin = sanitize_d(emin);
    if (emax < 1e-6) emax = 1e-6;
    if (emin < 1e-6) emin = 1e-6;
    double ratio = emax / emin;
    if (ratio < 1.0)   ratio = 1.0;
    if (ratio > 1.0e6) ratio = 1.0e6;

    double l = log(ratio);
    #pragma unroll
    for (int m = 16; m > 0; m >>= 1)
        l += __shfl_xor_sync(0xffffffffu, l, m);

    if (b == 0) out[0] = (float)(-l / (double)B_DIM);
}

extern "C" void kernel_launch(void* const* d_in, const int* in_sizes, int n_in,
                              void* d_out, int out_size) {
    (void)in_sizes; (void)n_in; (void)out_size;
    const float* g = (const float*)d_in[0];
    float* out = (float*)d_out;
    moments_kernel<<<B_DIM * CHUNKS, THREADS>>>(g);
    finalize_kernel<<<1, 32>>>(out);
}

// round 4
// speedup vs baseline: 2.8163x; 2.8163x over previous
#include <cuda_runtime.h>
#include <cuda_bf16.h>
#include <math.h>

// PositionCollapseLoss: per batch covariance of pos (channels 0:3 of 14),
// eigvals of 3x3 symmetric, loss = -mean(log(clip(lmax/lmin,1,1e6)))
//
// Kernel 1: 9 raw fp32 moments per (batch, chunk) -> deterministic partials.
// Kernel 2: fp32 parallel finalize (warp per batch, analytic 3x3 eigvals).

#define B_DIM   32
#define N_PTS   65536
#define N_CH    14
#define CHUNKS  32          // blocks per batch; must be 32 (one warp lane each)
#define THREADS 256
#define PTS_PER_BLK (N_PTS / CHUNKS)   // 2048

__device__ float g_part[B_DIM * CHUNKS][9];

__global__ __launch_bounds__(THREADS)
void moments_kernel(const float* __restrict__ g) {
    const int blk = blockIdx.x;                 // 0 .. B*CHUNKS-1
    const int b   = blk / CHUNKS;
    const int c   = blk % CHUNKS;
    const int n0  = c * PTS_PER_BLK;

    const float* __restrict__ base = g + (size_t)b * (N_PTS * N_CH);

    float sx = 0.f, sy = 0.f, sz = 0.f;
    float sxx = 0.f, sxy = 0.f, sxz = 0.f;
    float syy = 0.f, syz = 0.f, szz = 0.f;

    #pragma unroll
    for (int it = 0; it < PTS_PER_BLK / THREADS; ++it) {
        const int i = n0 + it * THREADS + threadIdx.x;
        const int off = i * N_CH;               // fits int: < 13M
        // 56-byte point stride => always 8-byte aligned: float2 + scalar
        const float2 xy = *reinterpret_cast<const float2*>(base + off);
        const float  z  = base[off + 2];
        const float x = xy.x, y = xy.y;
        sx += x;  sy += y;  sz += z;
        sxx += x * x;  sxy += x * y;  sxz += x * z;
        syy += y * y;  syz += y * z;  szz += z * z;
    }

    float s[9] = {sx, sy, sz, sxx, sxy, sxz, syy, syz, szz};

    #pragma unroll
    for (int k = 0; k < 9; ++k) {
        #pragma unroll
        for (int m = 16; m > 0; m >>= 1)
            s[k] += __shfl_xor_sync(0xffffffffu, s[k], m);
    }

    __shared__ float sm[THREADS / 32][9];
    const int warp = threadIdx.x >> 5;
    const int lane = threadIdx.x & 31;
    if (lane == 0) {
        #pragma unroll
        for (int k = 0; k < 9; ++k) sm[warp][k] = s[k];
    }
    __syncthreads();

    if (warp == 0) {
        #pragma unroll
        for (int k = 0; k < 9; ++k) {
            float v = (lane < (THREADS / 32)) ? sm[lane][k] : 0.f;
            #pragma unroll
            for (int m = 4; m > 0; m >>= 1)
                v += __shfl_xor_sync(0xffffffffu, v, m);
            if (lane == 0) g_part[blk][k] = v;
        }
    }
}

__device__ __forceinline__ float sanitize_f(float x) {
    if (isnan(x)) x = 0.0f;
    if (x >  1.0e6f) x =  1.0e6f;
    if (x < -1.0e6f) x = -1.0e6f;
    return x;
}

__global__ __launch_bounds__(B_DIM * CHUNKS)
void finalize_kernel(float* __restrict__ out) {
    const int b    = threadIdx.x >> 5;   // batch = warp
    const int lane = threadIdx.x & 31;   // chunk = lane

    // Each lane loads its chunk's 9 partials (all loads in flight at once).
    float s[9];
    #pragma unroll
    for (int k = 0; k < 9; ++k) s[k] = g_part[b * CHUNKS + lane][k];

    // Tree-reduce across chunks (pairwise summation: good fp32 accuracy).
    #pragma unroll
    for (int k = 0; k < 9; ++k) {
        #pragma unroll
        for (int m = 16; m > 0; m >>= 1)
            s[k] += __shfl_xor_sync(0xffffffffu, s[k], m);
    }

    __shared__ float sh_log[B_DIM];

    if (lane == 0) {
        const float invN = 1.0f / (float)N_PTS;
        const float mx = s[0] * invN, my = s[1] * invN, mz = s[2] * invN;
        float cxx = s[3] * invN - mx * mx;
        float cxy = s[4] * invN - mx * my;
        float cxz = s[5] * invN - mx * mz;
        float cyy = s[6] * invN - my * my;
        float cyz = s[7] * invN - my * mz;
        float czz = s[8] * invN - mz * mz;

        cxx = sanitize_f(cxx); cxy = sanitize_f(cxy); cxz = sanitize_f(cxz);
        cyy = sanitize_f(cyy); cyz = sanitize_f(cyz); czz = sanitize_f(czz);

        // Analytic eigenvalues of symmetric 3x3 (trigonometric method)
        const float q  = (cxx + cyy + czz) * (1.0f / 3.0f);
        const float p1 = cxy * cxy + cxz * cxz + cyz * cyz;
        const float d1 = cxx - q, d2 = cyy - q, d3 = czz - q;
        const float p2 = d1 * d1 + d2 * d2 + d3 * d3 + 2.0f * p1;

        float emax, emin;
        if (p2 <= 0.0f) {
            emax = q; emin = q;
        } else {
            const float p  = sqrtf(p2 * (1.0f / 6.0f));
            const float ip = 1.0f / p;
            const float b11 = d1 * ip, b22 = d2 * ip, b33 = d3 * ip;
            const float b12 = cxy * ip, b13 = cxz * ip, b23 = cyz * ip;
            float detB = b11 * (b22 * b33 - b23 * b23)
                       - b12 * (b12 * b33 - b23 * b13)
                       + b13 * (b12 * b23 - b22 * b13);
            float r = detB * 0.5f;
            r = fminf(1.0f, fmaxf(-1.0f, r));
            const float phi = acosf(r) * (1.0f / 3.0f);
            emax = q + 2.0f * p * cosf(phi);
            emin = q + 2.0f * p * cosf(phi + 2.0943951023931953f); // +2pi/3
        }

        emax = fmaxf(sanitize_f(emax), 1e-6f);
        emin = fmaxf(sanitize_f(emin), 1e-6f);
        float ratio = emax / emin;
        ratio = fminf(1.0e6f, fmaxf(1.0f, ratio));
        sh_log[b] = logf(ratio);
    }
    __syncthreads();

    if (threadIdx.x < 32) {
        float l = sh_log[threadIdx.x];
        #pragma unroll
        for (int m = 16; m > 0; m >>= 1)
            l += __shfl_xor_sync(0xffffffffu, l, m);
        if (threadIdx.x == 0) out[0] = -l * (1.0f / (float)B_DIM);
    }
}

extern "C" void kernel_launch(void* const* d_in, const int* in_sizes, int n_in,
                              void* d_out, int out_size) {
    (void)in_sizes; (void)n_in; (void)out_size;
    const float* g = (const float*)d_in[0];
    float* out = (float*)d_out;
    moments_kernel<<<B_DIM * CHUNKS, THREADS>>>(g);
    finalize_kernel<<<1, B_DIM * CHUNKS>>>(out);
}